// round 2
// baseline (speedup 1.0000x reference)
#include <cuda_runtime.h>

#define NMAX 100000
#define NSEG 32
#define PP 8
#define TT 8
#define FF 32
#define TF 256  // TT*FF

__device__ __align__(16) float g_e[NMAX * PP];        // exp(h)
__device__ __align__(16) float g_dinv[NSEG * PP];     // 1/(segsum + eps)
__device__ int g_starts[NSEG + 1];

// ---------------- kernel 1: tiny MLP + exp ----------------
__global__ void mlp_kernel(const float* __restrict__ pos,
                           const float* __restrict__ W1, const float* __restrict__ b1,
                           const float* __restrict__ W2, const float* __restrict__ b2,
                           int N) {
    __shared__ float sW1[24], sb1[8], sW2[64], sb2[8];
    int tid = threadIdx.x;
    if (tid < 24) sW1[tid] = W1[tid];
    else if (tid >= 32 && tid < 40) sb1[tid - 32] = b1[tid - 32];
    else if (tid >= 64 && tid < 128) sW2[tid - 64] = W2[tid - 64];
    else if (tid >= 128 && tid < 136) sb2[tid - 128] = b2[tid - 128];
    __syncthreads();

    int i = blockIdx.x * blockDim.x + tid;
    if (i >= N) return;

    float p0 = pos[i * 3 + 0], p1 = pos[i * 3 + 1], p2 = pos[i * 3 + 2];

    float hid[8];
#pragma unroll
    for (int j = 0; j < 8; j++) {
        float v = fmaf(p0, sW1[0 * 8 + j], fmaf(p1, sW1[1 * 8 + j], fmaf(p2, sW1[2 * 8 + j], sb1[j])));
        hid[j] = v > 0.f ? v : expm1f(v);   // ELU (alpha=1)
    }
    float e[8];
#pragma unroll
    for (int p = 0; p < 8; p++) {
        float v = sb2[p];
#pragma unroll
        for (int j = 0; j < 8; j++) v = fmaf(hid[j], sW2[j * 8 + p], v);
        e[p] = expf(v);                      // TAU = 1; max-subtraction folded out (see analysis)
    }
    float4* outp = reinterpret_cast<float4*>(&g_e[(size_t)i * 8]);
    outp[0] = make_float4(e[0], e[1], e[2], e[3]);
    outp[1] = make_float4(e[4], e[5], e[6], e[7]);
}

// ---------------- kernel 2: segment boundaries (seg is sorted) ----------------
__global__ void bounds_kernel(const int* __restrict__ seg, int N) {
    int t = threadIdx.x;
    if (t > NSEG) return;
    int lo = 0, hi = N;
    while (lo < hi) {
        int mid = (lo + hi) >> 1;
        if (seg[mid] < t) lo = mid + 1; else hi = mid;
    }
    g_starts[t] = lo;
}

// ---------------- kernel 3: per-segment sums of e -> dinv ----------------
__global__ void sums_kernel() {
    int b = blockIdx.x;
    int start = g_starts[b], end = g_starts[b + 1];
    float part[8];
#pragma unroll
    for (int p = 0; p < 8; p++) part[p] = 0.f;

    for (int i = start + (int)threadIdx.x; i < end; i += 256) {
        const float4* ep = reinterpret_cast<const float4*>(&g_e[(size_t)i * 8]);
        float4 a = ep[0], c = ep[1];
        part[0] += a.x; part[1] += a.y; part[2] += a.z; part[3] += a.w;
        part[4] += c.x; part[5] += c.y; part[6] += c.z; part[7] += c.w;
    }
#pragma unroll
    for (int p = 0; p < 8; p++)
#pragma unroll
        for (int off = 16; off > 0; off >>= 1)
            part[p] += __shfl_down_sync(0xffffffffu, part[p], off);

    __shared__ float sh[8][8];
    int w = threadIdx.x >> 5, l = threadIdx.x & 31;
    if (l == 0) {
#pragma unroll
        for (int p = 0; p < 8; p++) sh[w][p] = part[p];
    }
    __syncthreads();
    if (threadIdx.x < 8) {
        float s = 0.f;
#pragma unroll
        for (int w2 = 0; w2 < 8; w2++) s += sh[w2][threadIdx.x];
        g_dinv[b * 8 + threadIdx.x] = 1.0f / (s + 1e-16f);
    }
}

// ---------------- kernel 4: main reduction ----------------
__device__ __forceinline__ void flush_acc(float acc[8][4], int segb, int t, int fq,
                                          float* __restrict__ out) {
    const float4* dp = reinterpret_cast<const float4*>(&g_dinv[segb * 8]);
    float4 d0 = __ldg(dp), d1 = __ldg(dp + 1);
    float dv[8] = {d0.x, d0.y, d0.z, d0.w, d1.x, d1.y, d1.z, d1.w};
#pragma unroll
    for (int p = 0; p < 8; p++) {
        int base = ((segb * TT + t) * PP + p) * FF + fq * 4;
        atomicAdd(&out[base + 0], acc[p][0] * dv[p]);
        atomicAdd(&out[base + 1], acc[p][1] * dv[p]);
        atomicAdd(&out[base + 2], acc[p][2] * dv[p]);
        atomicAdd(&out[base + 3], acc[p][3] * dv[p]);
        acc[p][0] = acc[p][1] = acc[p][2] = acc[p][3] = 0.f;
    }
}

__global__ void __launch_bounds__(256, 4)
main_kernel(const float* __restrict__ x, const int* __restrict__ seg,
            float* __restrict__ out, int N, int chunk) {
    int tid = threadIdx.x;
    int sub  = tid >> 6;        // which of 4 concurrent nodes
    int item = tid & 63;        // (t, f4) work item
    int t  = item >> 3;
    int fq = item & 7;          // float4 index along F

    int i0 = blockIdx.x * chunk;
    if (i0 >= N) return;
    int iEnd = min(i0 + chunk, N);

    float acc[8][4];
#pragma unroll
    for (int p = 0; p < 8; p++) {
        acc[p][0] = acc[p][1] = acc[p][2] = acc[p][3] = 0.f;
    }
    int cur = -1;

    for (int i = i0 + sub; i < iEnd; i += 4) {
        int s = __ldg(&seg[i]);
        if (s != cur) {
            if (cur >= 0) flush_acc(acc, cur, t, fq, out);
            cur = s;
        }
        float4 xv = __ldg(reinterpret_cast<const float4*>(&x[(size_t)i * TF + item * 4]));
        const float4* ep = reinterpret_cast<const float4*>(&g_e[(size_t)i * 8]);
        float4 ea = __ldg(ep), eb = __ldg(ep + 1);
        float ev[8] = {ea.x, ea.y, ea.z, ea.w, eb.x, eb.y, eb.z, eb.w};
#pragma unroll
        for (int p = 0; p < 8; p++) {
            acc[p][0] = fmaf(ev[p], xv.x, acc[p][0]);
            acc[p][1] = fmaf(ev[p], xv.y, acc[p][1]);
            acc[p][2] = fmaf(ev[p], xv.z, acc[p][2]);
            acc[p][3] = fmaf(ev[p], xv.w, acc[p][3]);
        }
    }
    if (cur >= 0) flush_acc(acc, cur, t, fq, out);
}

// ---------------- launch ----------------
extern "C" void kernel_launch(void* const* d_in, const int* in_sizes, int n_in,
                              void* d_out, int out_size) {
    const float* pos = (const float*)d_in[0];
    const float* x   = (const float*)d_in[1];
    const int*   seg = (const int*)d_in[2];
    const float* W1  = (const float*)d_in[3];
    const float* b1  = (const float*)d_in[4];
    const float* W2  = (const float*)d_in[5];
    const float* b2  = (const float*)d_in[6];
    float* out = (float*)d_out;

    int N = in_sizes[2];  // seg element count

    cudaMemsetAsync(d_out, 0, (size_t)out_size * sizeof(float));

    mlp_kernel<<<(N + 255) / 256, 256>>>(pos, W1, b1, W2, b2, N);
    bounds_kernel<<<1, 64>>>(seg, N);
    sums_kernel<<<NSEG, 256>>>();

    const int G = 148 * 4;  // one full wave at 4 CTAs/SM
    int chunk = (N + G - 1) / G;
    main_kernel<<<G, 256>>>(x, seg, out, N, chunk);
}

// round 3
// speedup vs baseline: 1.3195x; 1.3195x over previous
#include <cuda_runtime.h>

#define NMAX 100000
#define NSEG 32
#define PP 8
#define TT 8
#define FF 32
#define TF 256  // TT*FF

__device__ __align__(16) float g_e[NMAX * PP];        // exp(h)
__device__ __align__(16) float g_dinv[NSEG * PP];     // 1/(segsum + eps)
__device__ int g_starts[NSEG + 1];

// ---------------- kernel 1: tiny MLP + exp (+ segment bounds in block 0) ----------------
__global__ void mlp_kernel(const float* __restrict__ pos,
                           const float* __restrict__ W1, const float* __restrict__ b1,
                           const float* __restrict__ W2, const float* __restrict__ b2,
                           const int* __restrict__ seg, int N) {
    __shared__ float sW1[24], sb1[8], sW2[64], sb2[8];
    int tid = threadIdx.x;
    if (tid < 24) sW1[tid] = W1[tid];
    else if (tid >= 32 && tid < 40) sb1[tid - 32] = b1[tid - 32];
    else if (tid >= 64 && tid < 128) sW2[tid - 64] = W2[tid - 64];
    else if (tid >= 128 && tid < 136) sb2[tid - 128] = b2[tid - 128];

    // block 0: also compute segment start offsets (seg is sorted)
    if (blockIdx.x == 0 && tid >= 192 && tid <= 192 + NSEG) {
        int t = tid - 192;
        int lo = 0, hi = N;
        while (lo < hi) {
            int mid = (lo + hi) >> 1;
            if (seg[mid] < t) lo = mid + 1; else hi = mid;
        }
        g_starts[t] = lo;
    }
    __syncthreads();

    int i = blockIdx.x * blockDim.x + tid;
    if (i >= N) return;

    float p0 = pos[i * 3 + 0], p1 = pos[i * 3 + 1], p2 = pos[i * 3 + 2];

    float hid[8];
#pragma unroll
    for (int j = 0; j < 8; j++) {
        float v = fmaf(p0, sW1[0 * 8 + j], fmaf(p1, sW1[1 * 8 + j], fmaf(p2, sW1[2 * 8 + j], sb1[j])));
        hid[j] = v > 0.f ? v : expm1f(v);   // ELU (alpha=1)
    }
    float e[8];
#pragma unroll
    for (int p = 0; p < 8; p++) {
        float v = sb2[p];
#pragma unroll
        for (int j = 0; j < 8; j++) v = fmaf(hid[j], sW2[j * 8 + p], v);
        e[p] = expf(v);                      // TAU = 1; max-subtraction folded out (eps scale-invariant to 1e-16 rel)
    }
    float4* outp = reinterpret_cast<float4*>(&g_e[(size_t)i * 8]);
    outp[0] = make_float4(e[0], e[1], e[2], e[3]);
    outp[1] = make_float4(e[4], e[5], e[6], e[7]);
}

// ---------------- kernel 2: per-segment sums of e -> dinv ----------------
__global__ void sums_kernel() {
    int b = blockIdx.x;
    int start = g_starts[b], end = g_starts[b + 1];
    float part[8];
#pragma unroll
    for (int p = 0; p < 8; p++) part[p] = 0.f;

    for (int i = start + (int)threadIdx.x; i < end; i += 256) {
        const float4* ep = reinterpret_cast<const float4*>(&g_e[(size_t)i * 8]);
        float4 a = ep[0], c = ep[1];
        part[0] += a.x; part[1] += a.y; part[2] += a.z; part[3] += a.w;
        part[4] += c.x; part[5] += c.y; part[6] += c.z; part[7] += c.w;
    }
#pragma unroll
    for (int p = 0; p < 8; p++)
#pragma unroll
        for (int off = 16; off > 0; off >>= 1)
            part[p] += __shfl_down_sync(0xffffffffu, part[p], off);

    __shared__ float sh[8][8];
    int w = threadIdx.x >> 5, l = threadIdx.x & 31;
    if (l == 0) {
#pragma unroll
        for (int p = 0; p < 8; p++) sh[w][p] = part[p];
    }
    __syncthreads();
    if (threadIdx.x < 8) {
        float s = 0.f;
#pragma unroll
        for (int w2 = 0; w2 < 8; w2++) s += sh[w2][threadIdx.x];
        g_dinv[b * 8 + threadIdx.x] = 1.0f / (s + 1e-16f);
    }
}

// ---------------- kernel 3: main reduction ----------------
__device__ __forceinline__ void flush_acc(float acc[8][4], int segb, int t, int fq,
                                          float* __restrict__ out) {
    const float4* dp = reinterpret_cast<const float4*>(&g_dinv[segb * 8]);
    float4 d0 = __ldg(dp), d1 = __ldg(dp + 1);
    float dv[8] = {d0.x, d0.y, d0.z, d0.w, d1.x, d1.y, d1.z, d1.w};
#pragma unroll
    for (int p = 0; p < 8; p++) {
        int base = ((segb * TT + t) * PP + p) * FF + fq * 4;
        atomicAdd(&out[base + 0], acc[p][0] * dv[p]);
        atomicAdd(&out[base + 1], acc[p][1] * dv[p]);
        atomicAdd(&out[base + 2], acc[p][2] * dv[p]);
        atomicAdd(&out[base + 3], acc[p][3] * dv[p]);
        acc[p][0] = acc[p][1] = acc[p][2] = acc[p][3] = 0.f;
    }
}

__global__ void __launch_bounds__(256, 3)
main_kernel(const float* __restrict__ x, const int* __restrict__ seg,
            float* __restrict__ out, int N, int chunk) {
    int tid = threadIdx.x;
    int sub  = tid >> 6;        // which of 4 concurrent nodes
    int item = tid & 63;        // (t, f4) work item
    int t  = item >> 3;
    int fq = item & 7;          // float4 index along F

    int i0 = blockIdx.x * chunk;
    if (i0 >= N) return;
    int iEnd = min(i0 + chunk, N);

    float acc[8][4];
#pragma unroll
    for (int p = 0; p < 8; p++)
        acc[p][0] = acc[p][1] = acc[p][2] = acc[p][3] = 0.f;

    const float4* xbase = reinterpret_cast<const float4*>(x) + item;  // +64 per node
    const float4* ebase = reinterpret_cast<const float4*>(g_e);       // +2 per node

    int i = i0 + sub;
    while (i < iEnd) {
        int s = __ldg(&seg[i]);                  // one load per segment-run
        int bend = min(iEnd, g_starts[s + 1]);   // run end (branch-free inner loop)

        // ---- unroll x2: two nodes in flight ----
        for (; i + 4 < bend; i += 8) {
            float4 xv0 = __ldcs(xbase + (size_t)i * 64);
            float4 ea0 = __ldg(ebase + (size_t)i * 2);
            float4 eb0 = __ldg(ebase + (size_t)i * 2 + 1);
            float4 xv1 = __ldcs(xbase + (size_t)(i + 4) * 64);
            float4 ea1 = __ldg(ebase + (size_t)(i + 4) * 2);
            float4 eb1 = __ldg(ebase + (size_t)(i + 4) * 2 + 1);

            float ev0[8] = {ea0.x, ea0.y, ea0.z, ea0.w, eb0.x, eb0.y, eb0.z, eb0.w};
            float ev1[8] = {ea1.x, ea1.y, ea1.z, ea1.w, eb1.x, eb1.y, eb1.z, eb1.w};
#pragma unroll
            for (int p = 0; p < 8; p++) {
                acc[p][0] = fmaf(ev0[p], xv0.x, acc[p][0]);
                acc[p][1] = fmaf(ev0[p], xv0.y, acc[p][1]);
                acc[p][2] = fmaf(ev0[p], xv0.z, acc[p][2]);
                acc[p][3] = fmaf(ev0[p], xv0.w, acc[p][3]);
            }
#pragma unroll
            for (int p = 0; p < 8; p++) {
                acc[p][0] = fmaf(ev1[p], xv1.x, acc[p][0]);
                acc[p][1] = fmaf(ev1[p], xv1.y, acc[p][1]);
                acc[p][2] = fmaf(ev1[p], xv1.z, acc[p][2]);
                acc[p][3] = fmaf(ev1[p], xv1.w, acc[p][3]);
            }
        }
        // ---- remainder (0 or 1 node) ----
        for (; i < bend; i += 4) {
            float4 xv = __ldcs(xbase + (size_t)i * 64);
            float4 ea = __ldg(ebase + (size_t)i * 2);
            float4 eb = __ldg(ebase + (size_t)i * 2 + 1);
            float ev[8] = {ea.x, ea.y, ea.z, ea.w, eb.x, eb.y, eb.z, eb.w};
#pragma unroll
            for (int p = 0; p < 8; p++) {
                acc[p][0] = fmaf(ev[p], xv.x, acc[p][0]);
                acc[p][1] = fmaf(ev[p], xv.y, acc[p][1]);
                acc[p][2] = fmaf(ev[p], xv.z, acc[p][2]);
                acc[p][3] = fmaf(ev[p], xv.w, acc[p][3]);
            }
        }
        flush_acc(acc, s, t, fq, out);
    }
}

// ---------------- launch ----------------
extern "C" void kernel_launch(void* const* d_in, const int* in_sizes, int n_in,
                              void* d_out, int out_size) {
    const float* pos = (const float*)d_in[0];
    const float* x   = (const float*)d_in[1];
    const int*   seg = (const int*)d_in[2];
    const float* W1  = (const float*)d_in[3];
    const float* b1  = (const float*)d_in[4];
    const float* W2  = (const float*)d_in[5];
    const float* b2  = (const float*)d_in[6];
    float* out = (float*)d_out;

    int N = in_sizes[2];  // seg element count

    cudaMemsetAsync(d_out, 0, (size_t)out_size * sizeof(float));

    mlp_kernel<<<(N + 255) / 256, 256>>>(pos, W1, b1, W2, b2, seg, N);
    sums_kernel<<<NSEG, 256>>>();

    const int G = 148 * 3;  // one full wave at 3 CTAs/SM (regs ~80)
    int chunk = (N + G - 1) / G;
    main_kernel<<<G, 256>>>(x, seg, out, N, chunk);
}